// round 8
// baseline (speedup 1.0000x reference)
#include <cuda_runtime.h>
#include <cstdint>

// KDPointToPointLoss: loss[b] = (1/(3N)) * sum_n min_m ||s[b,:,n] - t[b,:,m]||^2
// B=8, C=3, N=M=4096.
//
// Dense fp32 is pinned at the FMA-pipe roofline (~22us: 3 FMA x 134M pairs).
// This version prunes pairs EXACTLY via a 1D x-sort:
//   build: counting-sort targets+sources by x (256 bins); 64 chunks of 64
//          sorted targets with exact x-bounds + monotone prefix/suffix bounds.
//   search: warp-uniform outward sweep over chunks; dense FFMA2 scan of each
//           non-pruned chunk; rigorous termination via monotone bounds.
// Result identical to dense (pruned chunks provably cannot contain the min).
// Output written at original source indices -> deterministic reduce order.

#define BATCH 8
#define NPTS  4096
#define MPTS  4096
#define BINS  256
#define NCH   64                 // target chunks
#define CHSZ  (MPTS / NCH)       // 64 targets per chunk
#define CHP   (CHSZ / 2)         // 32 pairs per chunk

__device__ int        g_hist[BATCH * 2 * BINS];
__device__ float4     g_ssort[BATCH * NPTS];    // sorted sources (x,y,z,|s|^2)
__device__ int        g_sidx [BATCH * NPTS];    // original index of sorted source
__device__ float4     g_tsort[BATCH * MPTS];    // sorted targets (x,y,z,|t|^2)
__device__ ulonglong2 g_tpack[BATCH * MPTS];    // pair-packed: [2p]={xx,yy},[2p+1]={zz,ww}
__device__ float      g_clo[BATCH * NCH], g_chi[BATCH * NCH];  // exact chunk x-bounds
__device__ float      g_Mpre[BATCH * NCH];      // prefix max of chi  (left-stop bound)
__device__ float      g_msuf[BATCH * NCH];      // suffix min of clo  (right-stop bound)
__device__ float      g_d2[BATCH * NPTS];       // min d2 at ORIGINAL index
__device__ float      g_s1[BATCH * 8];
__device__ int        g_cnt[BATCH];

__device__ __forceinline__ unsigned long long ffma2(
    unsigned long long a, unsigned long long b, unsigned long long c) {
    unsigned long long d;
    asm("fma.rn.f32x2 %0, %1, %2, %3;" : "=l"(d) : "l"(a), "l"(b), "l"(c));
    return d;
}
__device__ __forceinline__ unsigned long long pack2(float lo, float hi) {
    unsigned long long r;
    asm("mov.b64 %0, {%1, %2};" : "=l"(r) : "f"(lo), "f"(hi));
    return r;
}
__device__ __forceinline__ void unpack2(unsigned long long v, float& lo, float& hi) {
    asm("mov.b64 {%0, %1}, %2;" : "=f"(lo), "=f"(hi) : "l"(v));
}
__device__ __forceinline__ int bin_of(float x) {
    return min(BINS - 1, max(0, (int)((x + 4.0f) * 32.0f)));
}

// ---- build stage ----

__global__ void zero_kernel() {
    int i = blockIdx.x * blockDim.x + threadIdx.x;
    if (i < BATCH * 2 * BINS) g_hist[i] = 0;
    if (i < BATCH) g_cnt[i] = 0;
}

// grid (8 slices, 8 batches), 256 thr: histogram of x for targets + sources.
__global__ __launch_bounds__(256) void hist_kernel(
    const float* __restrict__ src, const float* __restrict__ tgt) {
    const int sl = blockIdx.x, b = blockIdx.y;
    const int i0 = sl * 512;
    const float* tb = tgt + (size_t)b * 3 * MPTS;
    const float* sb = src + (size_t)b * 3 * NPTS;
    for (int i = threadIdx.x; i < 512; i += 256) {
        atomicAdd(&g_hist[(b * 2 + 0) * BINS + bin_of(tb[i0 + i])], 1);
        atomicAdd(&g_hist[(b * 2 + 1) * BINS + bin_of(sb[i0 + i])], 1);
    }
}

// grid (2 arrays, 8 batches), 256 thr: scan bins, scatter points.
__global__ __launch_bounds__(256) void scatter_kernel(
    const float* __restrict__ src, const float* __restrict__ tgt) {
    __shared__ int off[BINS];
    __shared__ int tmp[BINS];
    const int arr = blockIdx.x, b = blockIdx.y, tid = threadIdx.x;

    int v = g_hist[(b * 2 + arr) * BINS + tid];
    tmp[tid] = v;
    __syncthreads();
    // Hillis-Steele inclusive scan over 256.
    for (int o = 1; o < BINS; o <<= 1) {
        int t = (tid >= o) ? tmp[tid - o] : 0;
        __syncthreads();
        tmp[tid] += t;
        __syncthreads();
    }
    off[tid] = tmp[tid] - v;   // exclusive
    __syncthreads();

    const float* p = (arr == 0) ? (tgt + (size_t)b * 3 * MPTS)
                                : (src + (size_t)b * 3 * NPTS);
    for (int i = tid; i < 4096; i += 256) {
        float x = p[i], y = p[4096 + i], z = p[2 * 4096 + i];
        int pos = atomicAdd(&off[bin_of(x)], 1);
        float4 q = make_float4(x, y, z, fmaf(x, x, fmaf(y, y, z * z)));
        if (arr == 0) {
            g_tsort[b * MPTS + pos] = q;
        } else {
            g_ssort[b * NPTS + pos] = q;
            g_sidx[b * NPTS + pos] = i;
        }
    }
}

// grid 8 (batch), 64 thr: per-chunk exact x-bounds + FFMA2 pair repack +
// monotone prefix/suffix termination bounds.
__global__ __launch_bounds__(NCH) void bounds_kernel() {
    const int b = blockIdx.x, c = threadIdx.x;
    const float4* tp = g_tsort + (size_t)b * MPTS + c * CHSZ;
    ulonglong2* op = g_tpack + (size_t)b * MPTS + c * CHSZ;
    float lo = 3.4e38f, hi = -3.4e38f;
#pragma unroll 4
    for (int p = 0; p < CHP; p++) {
        float4 t0 = tp[2 * p], t1 = tp[2 * p + 1];
        lo = fminf(lo, fminf(t0.x, t1.x));
        hi = fmaxf(hi, fmaxf(t0.x, t1.x));
        op[2 * p]     = make_ulonglong2(pack2(t0.x, t1.x), pack2(t0.y, t1.y));
        op[2 * p + 1] = make_ulonglong2(pack2(t0.z, t1.z), pack2(t0.w, t1.w));
    }
    g_clo[b * NCH + c] = lo;
    g_chi[b * NCH + c] = hi;
    __syncthreads();
    if (c == 0) {
        float M = -3.4e38f;
        for (int k = 0; k < NCH; k++) {
            M = fmaxf(M, g_chi[b * NCH + k]);
            g_Mpre[b * NCH + k] = M;   // max x over all chunks <= k
        }
        float m = 3.4e38f;
        for (int k = NCH - 1; k >= 0; k--) {
            m = fminf(m, g_clo[b * NCH + k]);
            g_msuf[b * NCH + k] = m;   // min x over all chunks >= k
        }
    }
}

// ---- search stage ----
// grid (64, 8), 64 thr: block = sorted sources [c0*64, c0*64+64), c0=blockIdx.x.
__global__ __launch_bounds__(64) void search_kernel() {
    __shared__ float sclo[NCH], schi[NCH], sM[NCH], sm[NCH];
    const int c0 = blockIdx.x, b = blockIdx.y, tid = threadIdx.x;

    sclo[tid] = g_clo[b * NCH + tid];
    schi[tid] = g_chi[b * NCH + tid];
    sM[tid]   = g_Mpre[b * NCH + tid];
    sm[tid]   = g_msuf[b * NCH + tid];
    __syncthreads();

    const float4 s = g_ssort[(size_t)b * NPTS + c0 * CHSZ + tid];
    const unsigned long long cx2 = pack2(-2.0f * s.x, -2.0f * s.x);
    const unsigned long long cy2 = pack2(-2.0f * s.y, -2.0f * s.y);
    const unsigned long long cz2 = pack2(-2.0f * s.z, -2.0f * s.z);
    const float sw = s.w;
    const ulonglong2* tpk = g_tpack + (size_t)b * MPTS;

    float best_sc = 3.4e38f;   // min over targets of (|t|^2 - 2 s.t); d2 = best_sc + sw

    // Dense FFMA2 scan of one chunk (warp-uniform c).
    auto scan_chunk = [&](int c) {
        const ulonglong2* p = tpk + c * CHSZ;
        float mL = 3.4e38f, mH = 3.4e38f;
#pragma unroll 8
        for (int j = 0; j < CHP; j++) {
            ulonglong2 vxy = p[2 * j];
            ulonglong2 vzw = p[2 * j + 1];
            unsigned long long acc = ffma2(cz2, vzw.x, vzw.y);
            acc = ffma2(cy2, vxy.y, acc);
            acc = ffma2(cx2, vxy.x, acc);
            float lo, hi;
            unpack2(acc, lo, hi);
            mL = fminf(mL, lo);
            mH = fminf(mH, hi);
        }
        best_sc = fminf(best_sc, fminf(mL, mH));
    };

    scan_chunk(c0);

    int L = c0 - 1, R = c0 + 1;
    bool doneL = (L < 0), doneR = (R >= NCH);
    while (!doneL || !doneR) {
        if (!doneL) {
            float bd2 = best_sc + sw;                  // current best d2 (per lane)
            float gap = s.x - sM[L];                   // lb gap to ALL chunks <= L
            if (__all_sync(0xFFFFFFFFu, gap > 0.0f && gap * gap > bd2)) {
                doneL = true;                          // nothing left of L can win
            } else {
                float d = fmaxf(fmaxf(sclo[L] - s.x, s.x - schi[L]), 0.0f);
                if (!__all_sync(0xFFFFFFFFu, d * d > bd2)) scan_chunk(L);
                if (--L < 0) doneL = true;
            }
        }
        if (!doneR) {
            float bd2 = best_sc + sw;
            float gap = sm[R] - s.x;                   // lb gap to ALL chunks >= R
            if (__all_sync(0xFFFFFFFFu, gap > 0.0f && gap * gap > bd2)) {
                doneR = true;
            } else {
                float d = fmaxf(fmaxf(sclo[R] - s.x, s.x - schi[R]), 0.0f);
                if (!__all_sync(0xFFFFFFFFu, d * d > bd2)) scan_chunk(R);
                if (++R >= NCH) doneR = true;
            }
        }
    }

    g_d2[(size_t)b * NPTS + g_sidx[(size_t)b * NPTS + c0 * CHSZ + tid]] = best_sc + sw;
}

// ---- reduce (fused last-block finish, deterministic order) ----
__global__ __launch_bounds__(256) void reduce_kernel(float* __restrict__ out) {
    __shared__ float sh[256];
    __shared__ int amLast;
    const int sl = blockIdx.x, b = blockIdx.y;
    const int i0 = sl * (NPTS / 8);
    float s = 0.0f;
    for (int i = threadIdx.x; i < NPTS / 8; i += 256)
        s += g_d2[(size_t)b * NPTS + i0 + i];
    sh[threadIdx.x] = s;
    __syncthreads();
    for (int o = 128; o > 0; o >>= 1) {
        if (threadIdx.x < o) sh[threadIdx.x] += sh[threadIdx.x + o];
        __syncthreads();
    }
    if (threadIdx.x == 0) {
        g_s1[b * 8 + sl] = sh[0];
        __threadfence();
        int prev = atomicAdd(&g_cnt[b], 1);
        amLast = (prev == 7);
    }
    __syncthreads();
    if (amLast && threadIdx.x == 0) {
        __threadfence();
        float tot = 0.0f;
#pragma unroll
        for (int t = 0; t < 8; t++) tot += g_s1[b * 8 + t];
        out[b] = tot * (1.0f / (3.0f * NPTS));
        g_cnt[b] = 0;   // reset for graph replay
    }
}

extern "C" void kernel_launch(void* const* d_in, const int* in_sizes, int n_in,
                              void* d_out, int out_size) {
    const float* src = (const float*)d_in[0];  // [B,3,N]
    const float* tgt = (const float*)d_in[1];  // [B,3,M]
    float* out = (float*)d_out;                // [B]

    zero_kernel<<<(BATCH * 2 * BINS + 511) / 512, 512>>>();
    hist_kernel<<<dim3(8, BATCH), 256>>>(src, tgt);
    scatter_kernel<<<dim3(2, BATCH), 256>>>(src, tgt);
    bounds_kernel<<<BATCH, NCH>>>();
    search_kernel<<<dim3(NCH, BATCH), 64>>>();
    reduce_kernel<<<dim3(8, BATCH), 256>>>(out);
}

// round 9
// speedup vs baseline: 6.5372x; 6.5372x over previous
#include <cuda_runtime.h>
#include <cstdint>

// KDPointToPointLoss: loss[b] = (1/(3N)) * sum_n min_m ||s[b,:,n] - t[b,:,m]||^2
// B=8, C=3, N=M=4096 (fixed by dataset).
//
// Dense exact fp32, at the FMA-pipe roofline (~22us for 403M FMAs).
// score(n,m) = |t_m|^2 - 2 s_n.t_m (monotone in d2). Targets in smem as two
// interleaved 16B words per pair -> 2x LDS.128 per j2; fma.rn.f32x2 inner loop.
// Grid (tgt x src x batch) = 8x8x8 = 512 blocks (best-measured config).
// Partials = 1MB (TSPLIT=8); single fused reduce with counter-based
// last-block finish (fixed summation order -> deterministic).

#define BATCH 8
#define NPTS  4096
#define MPTS  4096

#define THREADS   128
#define ILP       4                       // source points per thread
#define SRC_PER_BLOCK (THREADS * ILP)     // 512
#define SRC_CHUNKS (NPTS / SRC_PER_BLOCK) // 8
#define TSPLIT    8                       // target splits
#define TC        (MPTS / TSPLIT)         // 512 targets per block
#define TC2       (TC / 2)                // 256 packed pairs

#define RSLICES   32                      // reduce: point-slices per batch
#define RPTS      (NPTS / RSLICES)        // 128 points per reduce block

__device__ float g_part[TSPLIT * BATCH * NPTS];   // partial min d2 per (ts,b,n)
__device__ float g_s1[BATCH * RSLICES];           // per-slice sums
__device__ int   g_cnt[BATCH];                    // arrival counters (reset per run)

__device__ __forceinline__ unsigned long long ffma2(
    unsigned long long a, unsigned long long b, unsigned long long c) {
    unsigned long long d;
    asm("fma.rn.f32x2 %0, %1, %2, %3;" : "=l"(d) : "l"(a), "l"(b), "l"(c));
    return d;
}
__device__ __forceinline__ unsigned long long pack2(float lo, float hi) {
    unsigned long long r;
    asm("mov.b64 %0, {%1, %2};" : "=l"(r) : "f"(lo), "f"(hi));
    return r;
}
__device__ __forceinline__ void unpack2(unsigned long long v, float& lo, float& hi) {
    asm("mov.b64 {%0, %1}, %2;" : "=f"(lo), "=f"(hi) : "l"(v));
}

__global__ __launch_bounds__(THREADS) void nn_kernel(
    const float* __restrict__ src, const float* __restrict__ tgt) {
    // Interleaved: sxy[j2] = {packed x pair, packed y pair},
    //              szw[j2] = {packed z pair, packed |t|^2 pair} -> LDS.128.
    __shared__ ulonglong2 sxy[TC2], szw[TC2];

    const int ts   = blockIdx.x;               // target split
    const int src0 = blockIdx.y * SRC_PER_BLOCK;
    const int b    = blockIdx.z;
    const int tid  = threadIdx.x;
    const int tgt0 = ts * TC;

    // Cooperative packed load of this target chunk (TC2=256, 2 iters).
    const float2* tx = (const float2*)(tgt + (size_t)b * 3 * MPTS + 0 * MPTS + tgt0);
    const float2* ty = (const float2*)(tgt + (size_t)b * 3 * MPTS + 1 * MPTS + tgt0);
    const float2* tz = (const float2*)(tgt + (size_t)b * 3 * MPTS + 2 * MPTS + tgt0);
    for (int j2 = tid; j2 < TC2; j2 += THREADS) {
        float2 x = tx[j2];
        float2 y = ty[j2];
        float2 z = tz[j2];
        float w0 = fmaf(x.x, x.x, fmaf(y.x, y.x, z.x * z.x));
        float w1 = fmaf(x.y, x.y, fmaf(y.y, y.y, z.y * z.y));
        sxy[j2] = make_ulonglong2(pack2(x.x, x.y), pack2(y.x, y.y));
        szw[j2] = make_ulonglong2(pack2(z.x, z.y), pack2(w0, w1));
    }

    // Per-thread source points: packed duplicated coefficients (-2s, -2s).
    const float* sb = src + (size_t)b * 3 * NPTS;
    unsigned long long cx2[ILP], cy2[ILP], cz2[ILP];
    float s2[ILP], mnLo[ILP], mnHi[ILP];
#pragma unroll
    for (int p = 0; p < ILP; p++) {
        int n = src0 + p * THREADS + tid;
        float sx = sb[0 * NPTS + n];
        float sy = sb[1 * NPTS + n];
        float sz = sb[2 * NPTS + n];
        cx2[p] = pack2(-2.0f * sx, -2.0f * sx);
        cy2[p] = pack2(-2.0f * sy, -2.0f * sy);
        cz2[p] = pack2(-2.0f * sz, -2.0f * sz);
        s2[p]  = fmaf(sx, sx, fmaf(sy, sy, sz * sz));
        mnLo[p] = 1e30f;
        mnHi[p] = 1e30f;
    }
    __syncthreads();

    // Main loop: per j2 (2 targets): 2 LDS.128 + ILP*(3 FFMA2 + 2 FMNMX).
#pragma unroll 4
    for (int j2 = 0; j2 < TC2; j2++) {
        ulonglong2 vxy = sxy[j2];
        ulonglong2 vzw = szw[j2];
#pragma unroll
        for (int p = 0; p < ILP; p++) {
            unsigned long long acc = ffma2(cz2[p], vzw.x, vzw.y);
            acc = ffma2(cy2[p], vxy.y, acc);
            acc = ffma2(cx2[p], vxy.x, acc);
            float lo, hi;
            unpack2(acc, lo, hi);
            mnLo[p] = fminf(mnLo[p], lo);
            mnHi[p] = fminf(mnHi[p], hi);
        }
    }

    // Store partial d2 (add |s|^2 now so the reduce is pure min+sum).
    float* part = g_part + ((size_t)ts * BATCH + b) * NPTS;
#pragma unroll
    for (int p = 0; p < ILP; p++) {
        int n = src0 + p * THREADS + tid;
        part[n] = fminf(mnLo[p], mnHi[p]) + s2[p];
    }
}

// Fused reduce: grid = (RSLICES, BATCH) = 256 blocks x 128 thr. Each thread
// mins TSPLIT=8 partials for its single point; block-sums; the LAST arriving
// block per batch (atomic counter) does the fixed-order RSLICES sum -> out[b]
// and resets the counter for graph replay. Deterministic: final summation
// order is fixed regardless of arrival order.
__global__ __launch_bounds__(128) void reduce_kernel(float* __restrict__ out) {
    __shared__ float sh[128];
    __shared__ int amLast;
    const int sl = blockIdx.x, b = blockIdx.y;
    const int n = sl * RPTS + threadIdx.x;     // RPTS == 128 == blockDim

    float m = g_part[(size_t)b * NPTS + n];    // ts = 0
#pragma unroll
    for (int t = 1; t < TSPLIT; t++)
        m = fminf(m, g_part[((size_t)t * BATCH + b) * NPTS + n]);

    sh[threadIdx.x] = m;
    __syncthreads();
    for (int o = 64; o > 0; o >>= 1) {
        if (threadIdx.x < o) sh[threadIdx.x] += sh[threadIdx.x + o];
        __syncthreads();
    }
    if (threadIdx.x == 0) {
        g_s1[b * RSLICES + sl] = sh[0];
        __threadfence();
        int prev = atomicAdd(&g_cnt[b], 1);
        amLast = (prev == RSLICES - 1);
    }
    __syncthreads();
    if (amLast && threadIdx.x == 0) {
        __threadfence();
        float tot = 0.0f;
#pragma unroll
        for (int t = 0; t < RSLICES; t++) tot += g_s1[b * RSLICES + t];
        out[b] = tot * (1.0f / (3.0f * NPTS));
        g_cnt[b] = 0;  // reset for next graph replay
    }
}

extern "C" void kernel_launch(void* const* d_in, const int* in_sizes, int n_in,
                              void* d_out, int out_size) {
    const float* src = (const float*)d_in[0];  // [B,3,N]
    const float* tgt = (const float*)d_in[1];  // [B,3,M]
    float* out = (float*)d_out;                // [B]

    dim3 grid(TSPLIT, SRC_CHUNKS, BATCH);      // 8 x 8 x 8 = 512 blocks
    nn_kernel<<<grid, THREADS>>>(src, tgt);

    dim3 rgrid(RSLICES, BATCH);                // 32 x 8 = 256 blocks
    reduce_kernel<<<rgrid, 128>>>(out);
}

// round 10
// speedup vs baseline: 7.0395x; 1.0768x over previous
#include <cuda_runtime.h>
#include <cstdint>

// KDPointToPointLoss: loss[b] = (1/(3N)) * sum_n min_m ||s[b,:,n] - t[b,:,m]||^2
// B=8, C=3, N=M=4096 (fixed by dataset).
//
// Dense exact fp32 (nn is at the FMA-pipe roofline, ~22us for 403M FMAs).
// score(n,m) = |t_m|^2 - 2 s_n.t_m (monotone in d2). Targets in smem as two
// interleaved 16B words per pair -> 2x LDS.128 per j2; fma.rn.f32x2 inner loop.
//
// Cross-target-split combine: enc(d2) = ~bits(d2). For d2 >= 0 float order
// reverses under ~, so min-d2 == max-enc and the max identity is 0. nn uses
// no-return atomicMax (REDG); __device__ zero-init IS the identity, and the
// reduce resets enc back to 0 after reading -> no init kernel, graph-replay
// safe, fully deterministic (max is exact; final sum order is fixed).

#define BATCH 8
#define NPTS  4096
#define MPTS  4096

#define THREADS   128
#define ILP       4                       // source points per thread
#define SRC_PER_BLOCK (THREADS * ILP)     // 512
#define SRC_CHUNKS (NPTS / SRC_PER_BLOCK) // 8
#define TSPLIT    16                      // target splits (best-measured nn config)
#define TC        (MPTS / TSPLIT)         // 256 targets per block
#define TC2       (TC / 2)                // 128 packed pairs

#define RSLICES   32                      // reduce: point-slices per batch
#define RPTS      (NPTS / RSLICES)        // 128 points per reduce block

__device__ unsigned int g_enc[BATCH * NPTS];  // ~bits(min d2); 0 = identity
__device__ float        g_s1[BATCH * RSLICES];
__device__ int          g_cnt[BATCH];

__device__ __forceinline__ unsigned long long ffma2(
    unsigned long long a, unsigned long long b, unsigned long long c) {
    unsigned long long d;
    asm("fma.rn.f32x2 %0, %1, %2, %3;" : "=l"(d) : "l"(a), "l"(b), "l"(c));
    return d;
}
__device__ __forceinline__ unsigned long long pack2(float lo, float hi) {
    unsigned long long r;
    asm("mov.b64 %0, {%1, %2};" : "=l"(r) : "f"(lo), "f"(hi));
    return r;
}
__device__ __forceinline__ void unpack2(unsigned long long v, float& lo, float& hi) {
    asm("mov.b64 {%0, %1}, %2;" : "=f"(lo), "=f"(hi) : "l"(v));
}

__global__ __launch_bounds__(THREADS) void nn_kernel(
    const float* __restrict__ src, const float* __restrict__ tgt) {
    // Interleaved: sxy[j2] = {packed x pair, packed y pair},
    //              szw[j2] = {packed z pair, packed |t|^2 pair} -> LDS.128.
    __shared__ ulonglong2 sxy[TC2], szw[TC2];

    const int ts   = blockIdx.x;               // target split
    const int src0 = blockIdx.y * SRC_PER_BLOCK;
    const int b    = blockIdx.z;
    const int tid  = threadIdx.x;
    const int tgt0 = ts * TC;

    // Cooperative packed load of this target chunk (TC2 == THREADS -> 1 iter).
    const float2* tx = (const float2*)(tgt + (size_t)b * 3 * MPTS + 0 * MPTS + tgt0);
    const float2* ty = (const float2*)(tgt + (size_t)b * 3 * MPTS + 1 * MPTS + tgt0);
    const float2* tz = (const float2*)(tgt + (size_t)b * 3 * MPTS + 2 * MPTS + tgt0);
    for (int j2 = tid; j2 < TC2; j2 += THREADS) {
        float2 x = tx[j2];
        float2 y = ty[j2];
        float2 z = tz[j2];
        float w0 = fmaf(x.x, x.x, fmaf(y.x, y.x, z.x * z.x));
        float w1 = fmaf(x.y, x.y, fmaf(y.y, y.y, z.y * z.y));
        sxy[j2] = make_ulonglong2(pack2(x.x, x.y), pack2(y.x, y.y));
        szw[j2] = make_ulonglong2(pack2(z.x, z.y), pack2(w0, w1));
    }

    // Per-thread source points: packed duplicated coefficients (-2s, -2s).
    const float* sb = src + (size_t)b * 3 * NPTS;
    unsigned long long cx2[ILP], cy2[ILP], cz2[ILP];
    float s2[ILP], mnLo[ILP], mnHi[ILP];
#pragma unroll
    for (int p = 0; p < ILP; p++) {
        int n = src0 + p * THREADS + tid;
        float sx = sb[0 * NPTS + n];
        float sy = sb[1 * NPTS + n];
        float sz = sb[2 * NPTS + n];
        cx2[p] = pack2(-2.0f * sx, -2.0f * sx);
        cy2[p] = pack2(-2.0f * sy, -2.0f * sy);
        cz2[p] = pack2(-2.0f * sz, -2.0f * sz);
        s2[p]  = fmaf(sx, sx, fmaf(sy, sy, sz * sz));
        mnLo[p] = 1e30f;
        mnHi[p] = 1e30f;
    }
    __syncthreads();

    // Main loop: per j2 (2 targets): 2 LDS.128 + ILP*(3 FFMA2 + 2 FMNMX).
#pragma unroll 4
    for (int j2 = 0; j2 < TC2; j2++) {
        ulonglong2 vxy = sxy[j2];
        ulonglong2 vzw = szw[j2];
#pragma unroll
        for (int p = 0; p < ILP; p++) {
            unsigned long long acc = ffma2(cz2[p], vzw.x, vzw.y);
            acc = ffma2(cy2[p], vxy.y, acc);
            acc = ffma2(cx2[p], vxy.x, acc);
            float lo, hi;
            unpack2(acc, lo, hi);
            mnLo[p] = fminf(mnLo[p], lo);
            mnHi[p] = fminf(mnHi[p], hi);
        }
    }

    // Combine across target splits: min-d2 == max-enc, identity 0.
    // No return value used -> compiles to REDG (no round trip).
#pragma unroll
    for (int p = 0; p < ILP; p++) {
        int n = src0 + p * THREADS + tid;
        float d2 = fmaxf(fminf(mnLo[p], mnHi[p]) + s2[p], 0.0f);
        atomicMax(&g_enc[b * NPTS + n], ~__float_as_uint(d2));
    }
}

// Fused reduce: grid (RSLICES, BATCH) = 256 blocks x 128 thr; one point per
// thread. Read enc once, decode, RESET to 0 (identity) for the next graph
// replay, block-sum, and the last-arriving block per batch does the
// fixed-order RSLICES sum -> out[b], then resets the counter.
__global__ __launch_bounds__(128) void reduce_kernel(float* __restrict__ out) {
    __shared__ float sh[128];
    __shared__ int amLast;
    const int sl = blockIdx.x, b = blockIdx.y;
    const int n = sl * RPTS + threadIdx.x;     // RPTS == 128 == blockDim

    unsigned int e = g_enc[b * NPTS + n];
    g_enc[b * NPTS + n] = 0u;                  // reset identity for next replay
    float d2 = __uint_as_float(~e);

    sh[threadIdx.x] = d2;
    __syncthreads();
    for (int o = 64; o > 0; o >>= 1) {
        if (threadIdx.x < o) sh[threadIdx.x] += sh[threadIdx.x + o];
        __syncthreads();
    }
    if (threadIdx.x == 0) {
        g_s1[b * RSLICES + sl] = sh[0];
        __threadfence();
        int prev = atomicAdd(&g_cnt[b], 1);
        amLast = (prev == RSLICES - 1);
    }
    __syncthreads();
    if (amLast && threadIdx.x == 0) {
        __threadfence();
        float tot = 0.0f;
#pragma unroll
        for (int t = 0; t < RSLICES; t++) tot += g_s1[b * RSLICES + t];
        out[b] = tot * (1.0f / (3.0f * NPTS));
        g_cnt[b] = 0;  // reset for next graph replay
    }
}

extern "C" void kernel_launch(void* const* d_in, const int* in_sizes, int n_in,
                              void* d_out, int out_size) {
    const float* src = (const float*)d_in[0];  // [B,3,N]
    const float* tgt = (const float*)d_in[1];  // [B,3,M]
    float* out = (float*)d_out;                // [B]

    dim3 grid(TSPLIT, SRC_CHUNKS, BATCH);      // 16 x 8 x 8 = 1024 blocks
    nn_kernel<<<grid, THREADS>>>(src, tgt);

    dim3 rgrid(RSLICES, BATCH);                // 32 x 8 = 256 blocks
    reduce_kernel<<<rgrid, 128>>>(out);
}

// round 11
// speedup vs baseline: 7.4918x; 1.0643x over previous
#include <cuda_runtime.h>
#include <cstdint>

// KDPointToPointLoss: loss[b] = (1/(3N)) * sum_n min_m ||s[b,:,n] - t[b,:,m]||^2
// B=8, C=3, N=M=4096 (fixed by dataset).
//
// Dense exact fp32 (nn is at the FMA-pipe roofline, ~22us for 403M FMAs).
// score(n,m) = |t_m|^2 - 2 s_n.t_m (monotone in d2). Targets in smem as two
// interleaved 16B words per pair -> 2x LDS.128 per j2; fma.rn.f32x2 inner loop.
//
// Cross-target-split combine: enc(d2) = ~bits(d2). For d2 >= 0, float order
// reverses under ~, so min-d2 == max-enc and the max identity is 0. nn uses
// no-return atomicMax (REDG); __device__ zero-init IS the identity.
//
// SINGLE KERNEL: the last-arriving block per batch (fence + counter acquire)
// reads all 4096 enc values of its batch (uint4), resets them to 0 for the
// next graph replay, decodes, block-sums in FIXED order -> out[b], resets the
// counter. Fully deterministic (max-combine exact; summation order fixed).

#define BATCH 8
#define NPTS  4096
#define MPTS  4096

#define THREADS   128
#define ILP       4                       // source points per thread
#define SRC_PER_BLOCK (THREADS * ILP)     // 512
#define SRC_CHUNKS (NPTS / SRC_PER_BLOCK) // 8
#define TSPLIT    16                      // target splits
#define TC        (MPTS / TSPLIT)         // 256 targets per block
#define TC2       (TC / 2)                // 128 packed pairs
#define BLOCKS_PER_BATCH (TSPLIT * SRC_CHUNKS)  // 128

__device__ unsigned int g_enc[BATCH * NPTS];  // ~bits(min d2); 0 = identity
__device__ int          g_cnt[BATCH];         // arrival counters (reset per run)

__device__ __forceinline__ unsigned long long ffma2(
    unsigned long long a, unsigned long long b, unsigned long long c) {
    unsigned long long d;
    asm("fma.rn.f32x2 %0, %1, %2, %3;" : "=l"(d) : "l"(a), "l"(b), "l"(c));
    return d;
}
__device__ __forceinline__ unsigned long long pack2(float lo, float hi) {
    unsigned long long r;
    asm("mov.b64 %0, {%1, %2};" : "=l"(r) : "f"(lo), "f"(hi));
    return r;
}
__device__ __forceinline__ void unpack2(unsigned long long v, float& lo, float& hi) {
    asm("mov.b64 {%0, %1}, %2;" : "=f"(lo), "=f"(hi) : "l"(v));
}

__global__ __launch_bounds__(THREADS) void nn_kernel(
    const float* __restrict__ src, const float* __restrict__ tgt,
    float* __restrict__ out) {
    // Interleaved: sxy[j2] = {packed x pair, packed y pair},
    //              szw[j2] = {packed z pair, packed |t|^2 pair} -> LDS.128.
    __shared__ ulonglong2 sxy[TC2], szw[TC2];
    __shared__ float shred[THREADS];
    __shared__ int amLast;

    const int ts   = blockIdx.x;               // target split
    const int src0 = blockIdx.y * SRC_PER_BLOCK;
    const int b    = blockIdx.z;
    const int tid  = threadIdx.x;
    const int tgt0 = ts * TC;

    // Cooperative packed load of this target chunk (TC2 == THREADS -> 1 iter).
    const float2* tx = (const float2*)(tgt + (size_t)b * 3 * MPTS + 0 * MPTS + tgt0);
    const float2* ty = (const float2*)(tgt + (size_t)b * 3 * MPTS + 1 * MPTS + tgt0);
    const float2* tz = (const float2*)(tgt + (size_t)b * 3 * MPTS + 2 * MPTS + tgt0);
    for (int j2 = tid; j2 < TC2; j2 += THREADS) {
        float2 x = tx[j2];
        float2 y = ty[j2];
        float2 z = tz[j2];
        float w0 = fmaf(x.x, x.x, fmaf(y.x, y.x, z.x * z.x));
        float w1 = fmaf(x.y, x.y, fmaf(y.y, y.y, z.y * z.y));
        sxy[j2] = make_ulonglong2(pack2(x.x, x.y), pack2(y.x, y.y));
        szw[j2] = make_ulonglong2(pack2(z.x, z.y), pack2(w0, w1));
    }

    // Per-thread source points: packed duplicated coefficients (-2s, -2s).
    const float* sb = src + (size_t)b * 3 * NPTS;
    unsigned long long cx2[ILP], cy2[ILP], cz2[ILP];
    float s2[ILP], mnLo[ILP], mnHi[ILP];
#pragma unroll
    for (int p = 0; p < ILP; p++) {
        int n = src0 + p * THREADS + tid;
        float sx = sb[0 * NPTS + n];
        float sy = sb[1 * NPTS + n];
        float sz = sb[2 * NPTS + n];
        cx2[p] = pack2(-2.0f * sx, -2.0f * sx);
        cy2[p] = pack2(-2.0f * sy, -2.0f * sy);
        cz2[p] = pack2(-2.0f * sz, -2.0f * sz);
        s2[p]  = fmaf(sx, sx, fmaf(sy, sy, sz * sz));
        mnLo[p] = 1e30f;
        mnHi[p] = 1e30f;
    }
    __syncthreads();

    // Main loop: per j2 (2 targets): 2 LDS.128 + ILP*(3 FFMA2 + 2 FMNMX).
#pragma unroll 4
    for (int j2 = 0; j2 < TC2; j2++) {
        ulonglong2 vxy = sxy[j2];
        ulonglong2 vzw = szw[j2];
#pragma unroll
        for (int p = 0; p < ILP; p++) {
            unsigned long long acc = ffma2(cz2[p], vzw.x, vzw.y);
            acc = ffma2(cy2[p], vxy.y, acc);
            acc = ffma2(cx2[p], vxy.x, acc);
            float lo, hi;
            unpack2(acc, lo, hi);
            mnLo[p] = fminf(mnLo[p], lo);
            mnHi[p] = fminf(mnHi[p], hi);
        }
    }

    // Combine across target splits: min-d2 == max-enc, identity 0.
    // No return value used -> compiles to REDG (no round trip).
#pragma unroll
    for (int p = 0; p < ILP; p++) {
        int n = src0 + p * THREADS + tid;
        float d2 = fmaxf(fminf(mnLo[p], mnHi[p]) + s2[p], 0.0f);
        atomicMax(&g_enc[b * NPTS + n], ~__float_as_uint(d2));
    }

    // ---- fused tail: last-arriving block of this batch finishes the loss ----
    if (tid == 0) {
        __threadfence();                       // publish REDG results
        int prev = atomicAdd(&g_cnt[b], 1);
        amLast = (prev == BLOCKS_PER_BATCH - 1);
    }
    __syncthreads();
    if (amLast) {
        __threadfence();                       // acquire all batches' writes
        // 128 threads x 8 uint4 = 4096 points; read, reset to identity, sum.
        uint4* pe = (uint4*)(g_enc + (size_t)b * NPTS);
        float s = 0.0f;
#pragma unroll
        for (int k = 0; k < NPTS / 4 / THREADS; k++) {   // 8 iterations
            int i = k * THREADS + tid;
            uint4 v = pe[i];
            pe[i] = make_uint4(0u, 0u, 0u, 0u);          // reset for replay
            s += __uint_as_float(~v.x) + __uint_as_float(~v.y) +
                 __uint_as_float(~v.z) + __uint_as_float(~v.w);
        }
        shred[tid] = s;
        __syncthreads();
        for (int o = THREADS / 2; o > 0; o >>= 1) {
            if (tid < o) shred[tid] += shred[tid + o];
            __syncthreads();
        }
        if (tid == 0) {
            out[b] = shred[0] * (1.0f / (3.0f * NPTS));
            g_cnt[b] = 0;                      // reset for next graph replay
        }
    }
}

extern "C" void kernel_launch(void* const* d_in, const int* in_sizes, int n_in,
                              void* d_out, int out_size) {
    const float* src = (const float*)d_in[0];  // [B,3,N]
    const float* tgt = (const float*)d_in[1];  // [B,3,M]
    float* out = (float*)d_out;                // [B]

    dim3 grid(TSPLIT, SRC_CHUNKS, BATCH);      // 16 x 8 x 8 = 1024 blocks
    nn_kernel<<<grid, THREADS>>>(src, tgt, out);
}

// round 12
// speedup vs baseline: 7.5358x; 1.0059x over previous
#include <cuda_runtime.h>
#include <cstdint>

// KDPointToPointLoss: loss[b] = (1/(3N)) * sum_n min_m ||s[b,:,n] - t[b,:,m]||^2
// B=8, C=3, N=M=4096 (fixed by dataset).
//
// Dense exact fp32 (main loop at the FMA-pipe roofline, ~22us for 403M FMAs).
// score(n,m) = |t_m|^2 - 2 s_n.t_m (monotone in d2). Targets in smem as two
// interleaved 16B words per pair -> 2x LDS.128 per j2; fma.rn.f32x2 inner loop.
//
// Combine: enc(d2) = ~bits(d2); for d2 >= 0 min-d2 == max-enc, identity 0.
// No-return atomicMax (REDG); zero-init IS the identity; finishers reset to 0.
//
// TWO-LEVEL FUSED REDUCTION (pipelined into the wave):
//  L1: last block of each (batch, src-chunk) 16-block group sums its own 512
//      points (1 uint4/thread) -> g_csum. Runs while other chunks still compute.
//  L2: last L1 finisher of each batch does a fixed-order 8-value sum -> out[b].
// All counters self-reset; summation orders fixed -> deterministic.

#define BATCH 8
#define NPTS  4096
#define MPTS  4096

#define THREADS   128
#define ILP       4                       // source points per thread
#define SRC_PER_BLOCK (THREADS * ILP)     // 512
#define SRC_CHUNKS (NPTS / SRC_PER_BLOCK) // 8
#define TSPLIT    16                      // target splits
#define TC        (MPTS / TSPLIT)         // 256 targets per block
#define TC2       (TC / 2)                // 128 packed pairs

__device__ unsigned int g_enc[BATCH * NPTS];          // ~bits(min d2); 0 = identity
__device__ float        g_csum[BATCH * SRC_CHUNKS];   // per-chunk sums
__device__ int          g_cnt1[BATCH * SRC_CHUNKS];   // L1 counters (to TSPLIT)
__device__ int          g_cnt2[BATCH];                // L2 counters (to SRC_CHUNKS)

__device__ __forceinline__ unsigned long long ffma2(
    unsigned long long a, unsigned long long b, unsigned long long c) {
    unsigned long long d;
    asm("fma.rn.f32x2 %0, %1, %2, %3;" : "=l"(d) : "l"(a), "l"(b), "l"(c));
    return d;
}
__device__ __forceinline__ unsigned long long pack2(float lo, float hi) {
    unsigned long long r;
    asm("mov.b64 %0, {%1, %2};" : "=l"(r) : "f"(lo), "f"(hi));
    return r;
}
__device__ __forceinline__ void unpack2(unsigned long long v, float& lo, float& hi) {
    asm("mov.b64 {%0, %1}, %2;" : "=f"(lo), "=f"(hi) : "l"(v));
}

__global__ __launch_bounds__(THREADS) void nn_kernel(
    const float* __restrict__ src, const float* __restrict__ tgt,
    float* __restrict__ out) {
    // Interleaved: sxy[j2] = {packed x pair, packed y pair},
    //              szw[j2] = {packed z pair, packed |t|^2 pair} -> LDS.128.
    __shared__ ulonglong2 sxy[TC2], szw[TC2];
    __shared__ float shred[THREADS];
    __shared__ int amLast1, amLast2;

    const int ts   = blockIdx.x;               // target split
    const int sc   = blockIdx.y;               // source chunk
    const int src0 = sc * SRC_PER_BLOCK;
    const int b    = blockIdx.z;
    const int tid  = threadIdx.x;
    const int tgt0 = ts * TC;

    // Cooperative packed load of this target chunk (TC2 == THREADS -> 1 iter).
    const float2* tx = (const float2*)(tgt + (size_t)b * 3 * MPTS + 0 * MPTS + tgt0);
    const float2* ty = (const float2*)(tgt + (size_t)b * 3 * MPTS + 1 * MPTS + tgt0);
    const float2* tz = (const float2*)(tgt + (size_t)b * 3 * MPTS + 2 * MPTS + tgt0);
    for (int j2 = tid; j2 < TC2; j2 += THREADS) {
        float2 x = tx[j2];
        float2 y = ty[j2];
        float2 z = tz[j2];
        float w0 = fmaf(x.x, x.x, fmaf(y.x, y.x, z.x * z.x));
        float w1 = fmaf(x.y, x.y, fmaf(y.y, y.y, z.y * z.y));
        sxy[j2] = make_ulonglong2(pack2(x.x, x.y), pack2(y.x, y.y));
        szw[j2] = make_ulonglong2(pack2(z.x, z.y), pack2(w0, w1));
    }

    // Per-thread source points: packed duplicated coefficients (-2s, -2s).
    const float* sb = src + (size_t)b * 3 * NPTS;
    unsigned long long cx2[ILP], cy2[ILP], cz2[ILP];
    float s2[ILP], mnLo[ILP], mnHi[ILP];
#pragma unroll
    for (int p = 0; p < ILP; p++) {
        int n = src0 + p * THREADS + tid;
        float sx = sb[0 * NPTS + n];
        float sy = sb[1 * NPTS + n];
        float sz = sb[2 * NPTS + n];
        cx2[p] = pack2(-2.0f * sx, -2.0f * sx);
        cy2[p] = pack2(-2.0f * sy, -2.0f * sy);
        cz2[p] = pack2(-2.0f * sz, -2.0f * sz);
        s2[p]  = fmaf(sx, sx, fmaf(sy, sy, sz * sz));
        mnLo[p] = 1e30f;
        mnHi[p] = 1e30f;
    }
    __syncthreads();

    // Main loop: per j2 (2 targets): 2 LDS.128 + ILP*(3 FFMA2 + 2 FMNMX).
#pragma unroll 4
    for (int j2 = 0; j2 < TC2; j2++) {
        ulonglong2 vxy = sxy[j2];
        ulonglong2 vzw = szw[j2];
#pragma unroll
        for (int p = 0; p < ILP; p++) {
            unsigned long long acc = ffma2(cz2[p], vzw.x, vzw.y);
            acc = ffma2(cy2[p], vxy.y, acc);
            acc = ffma2(cx2[p], vxy.x, acc);
            float lo, hi;
            unpack2(acc, lo, hi);
            mnLo[p] = fminf(mnLo[p], lo);
            mnHi[p] = fminf(mnHi[p], hi);
        }
    }

    // Combine across target splits: min-d2 == max-enc, identity 0 (REDG).
#pragma unroll
    for (int p = 0; p < ILP; p++) {
        int n = src0 + p * THREADS + tid;
        float d2 = fmaxf(fminf(mnLo[p], mnHi[p]) + s2[p], 0.0f);
        atomicMax(&g_enc[b * NPTS + n], ~__float_as_uint(d2));
    }

    // ---- L1: last block of this (batch, src-chunk) 16-block group ----
    if (tid == 0) {
        __threadfence();                       // publish REDG results
        int prev = atomicAdd(&g_cnt1[b * SRC_CHUNKS + sc], 1);
        amLast1 = (prev == TSPLIT - 1);
        if (amLast1) g_cnt1[b * SRC_CHUNKS + sc] = 0;  // reset for replay
    }
    __syncthreads();
    if (amLast1) {
        __threadfence();                       // acquire peers' REDG writes
        // 512 points: exactly one uint4 per thread; read, reset, decode, sum.
        uint4* pe = (uint4*)(g_enc + (size_t)b * NPTS + src0);
        uint4 v = pe[tid];
        pe[tid] = make_uint4(0u, 0u, 0u, 0u);  // reset identity for next replay
        shred[tid] = __uint_as_float(~v.x) + __uint_as_float(~v.y) +
                     __uint_as_float(~v.z) + __uint_as_float(~v.w);
        __syncthreads();
        for (int o = THREADS / 2; o > 0; o >>= 1) {
            if (tid < o) shred[tid] += shred[tid + o];
            __syncthreads();
        }
        // ---- L2: last chunk-finisher of this batch sums 8 chunk sums ----
        if (tid == 0) {
            g_csum[b * SRC_CHUNKS + sc] = shred[0];
            __threadfence();
            int prev = atomicAdd(&g_cnt2[b], 1);
            amLast2 = (prev == SRC_CHUNKS - 1);
            if (amLast2) g_cnt2[b] = 0;        // reset for replay
        }
        __syncthreads();
        if (amLast2 && tid == 0) {
            __threadfence();
            float tot = 0.0f;
#pragma unroll
            for (int t = 0; t < SRC_CHUNKS; t++) tot += g_csum[b * SRC_CHUNKS + t];
            out[b] = tot * (1.0f / (3.0f * NPTS));
        }
    }
}

extern "C" void kernel_launch(void* const* d_in, const int* in_sizes, int n_in,
                              void* d_out, int out_size) {
    const float* src = (const float*)d_in[0];  // [B,3,N]
    const float* tgt = (const float*)d_in[1];  // [B,3,M]
    float* out = (float*)d_out;                // [B]

    dim3 grid(TSPLIT, SRC_CHUNKS, BATCH);      // 16 x 8 x 8 = 1024 blocks
    nn_kernel<<<grid, THREADS>>>(src, tgt, out);
}

// round 13
// speedup vs baseline: 7.5625x; 1.0035x over previous
#include <cuda_runtime.h>
#include <cstdint>

// KDPointToPointLoss: loss[b] = (1/(3N)) * sum_n min_m ||s[b,:,n] - t[b,:,m]||^2
// B=8, C=3, N=M=4096 (fixed by dataset).
//
// Dense exact fp32. Main loop is pinned at the fp32 FMA-pipe wall (~22.3us:
// 402M FMAs; scalar rt2 and packed FFMA2 rt4 give identical pipe time — FFMA2
// just frees issue slots so we actually reach the wall).
// score(n,m) = |t_m|^2 - 2 s_n.t_m (monotone in d2). Targets in smem as two
// interleaved 16B words per pair -> 2x LDS.128 per j2; fma.rn.f32x2 inner loop.
//
// Combine: enc(d2) = ~bits(d2); for d2 >= 0 min-d2 == max-enc, identity 0.
// No-return atomicMax (REDG); zero-init IS the identity; finishers reset to 0.
//
// TSPLIT=32 -> 2048 blocks: per-block runtime ~1.6us halves the end-of-kernel
// straggler quantum. Two-level fused reduction pipelined into the wave:
//  L1: last of each (batch, src-chunk) 32-block group sums its 512 points.
//  L2: last L1 finisher per batch does a fixed-order 8-value sum -> out[b].
// All counters self-reset; summation orders fixed -> deterministic.

#define BATCH 8
#define NPTS  4096
#define MPTS  4096

#define THREADS   128
#define ILP       4                       // source points per thread
#define SRC_PER_BLOCK (THREADS * ILP)     // 512
#define SRC_CHUNKS (NPTS / SRC_PER_BLOCK) // 8
#define TSPLIT    32                      // target splits
#define TC        (MPTS / TSPLIT)         // 128 targets per block
#define TC2       (TC / 2)                // 64 packed pairs

__device__ unsigned int g_enc[BATCH * NPTS];          // ~bits(min d2); 0 = identity
__device__ float        g_csum[BATCH * SRC_CHUNKS];   // per-chunk sums
__device__ int          g_cnt1[BATCH * SRC_CHUNKS];   // L1 counters (to TSPLIT)
__device__ int          g_cnt2[BATCH];                // L2 counters (to SRC_CHUNKS)

__device__ __forceinline__ unsigned long long ffma2(
    unsigned long long a, unsigned long long b, unsigned long long c) {
    unsigned long long d;
    asm("fma.rn.f32x2 %0, %1, %2, %3;" : "=l"(d) : "l"(a), "l"(b), "l"(c));
    return d;
}
__device__ __forceinline__ unsigned long long pack2(float lo, float hi) {
    unsigned long long r;
    asm("mov.b64 %0, {%1, %2};" : "=l"(r) : "f"(lo), "f"(hi));
    return r;
}
__device__ __forceinline__ void unpack2(unsigned long long v, float& lo, float& hi) {
    asm("mov.b64 {%0, %1}, %2;" : "=f"(lo), "=f"(hi) : "l"(v));
}

__global__ __launch_bounds__(THREADS) void nn_kernel(
    const float* __restrict__ src, const float* __restrict__ tgt,
    float* __restrict__ out) {
    // Interleaved: sxy[j2] = {packed x pair, packed y pair},
    //              szw[j2] = {packed z pair, packed |t|^2 pair} -> LDS.128.
    __shared__ ulonglong2 sxy[TC2], szw[TC2];
    __shared__ float shred[THREADS];
    __shared__ int amLast1, amLast2;

    const int ts   = blockIdx.x;               // target split
    const int sc   = blockIdx.y;               // source chunk
    const int src0 = sc * SRC_PER_BLOCK;
    const int b    = blockIdx.z;
    const int tid  = threadIdx.x;
    const int tgt0 = ts * TC;

    // Cooperative packed load of this target chunk (TC2 = 64 < THREADS).
    const float2* tx = (const float2*)(tgt + (size_t)b * 3 * MPTS + 0 * MPTS + tgt0);
    const float2* ty = (const float2*)(tgt + (size_t)b * 3 * MPTS + 1 * MPTS + tgt0);
    const float2* tz = (const float2*)(tgt + (size_t)b * 3 * MPTS + 2 * MPTS + tgt0);
    if (tid < TC2) {
        int j2 = tid;
        float2 x = tx[j2];
        float2 y = ty[j2];
        float2 z = tz[j2];
        float w0 = fmaf(x.x, x.x, fmaf(y.x, y.x, z.x * z.x));
        float w1 = fmaf(x.y, x.y, fmaf(y.y, y.y, z.y * z.y));
        sxy[j2] = make_ulonglong2(pack2(x.x, x.y), pack2(y.x, y.y));
        szw[j2] = make_ulonglong2(pack2(z.x, z.y), pack2(w0, w1));
    }

    // Per-thread source points: packed duplicated coefficients (-2s, -2s).
    const float* sb = src + (size_t)b * 3 * NPTS;
    unsigned long long cx2[ILP], cy2[ILP], cz2[ILP];
    float s2[ILP], mnLo[ILP], mnHi[ILP];
#pragma unroll
    for (int p = 0; p < ILP; p++) {
        int n = src0 + p * THREADS + tid;
        float sx = sb[0 * NPTS + n];
        float sy = sb[1 * NPTS + n];
        float sz = sb[2 * NPTS + n];
        cx2[p] = pack2(-2.0f * sx, -2.0f * sx);
        cy2[p] = pack2(-2.0f * sy, -2.0f * sy);
        cz2[p] = pack2(-2.0f * sz, -2.0f * sz);
        s2[p]  = fmaf(sx, sx, fmaf(sy, sy, sz * sz));
        mnLo[p] = 1e30f;
        mnHi[p] = 1e30f;
    }
    __syncthreads();

    // Main loop: per j2 (2 targets): 2 LDS.128 + ILP*(3 FFMA2 + 2 FMNMX).
#pragma unroll 4
    for (int j2 = 0; j2 < TC2; j2++) {
        ulonglong2 vxy = sxy[j2];
        ulonglong2 vzw = szw[j2];
#pragma unroll
        for (int p = 0; p < ILP; p++) {
            unsigned long long acc = ffma2(cz2[p], vzw.x, vzw.y);
            acc = ffma2(cy2[p], vxy.y, acc);
            acc = ffma2(cx2[p], vxy.x, acc);
            float lo, hi;
            unpack2(acc, lo, hi);
            mnLo[p] = fminf(mnLo[p], lo);
            mnHi[p] = fminf(mnHi[p], hi);
        }
    }

    // Combine across target splits: min-d2 == max-enc, identity 0 (REDG).
#pragma unroll
    for (int p = 0; p < ILP; p++) {
        int n = src0 + p * THREADS + tid;
        float d2 = fmaxf(fminf(mnLo[p], mnHi[p]) + s2[p], 0.0f);
        atomicMax(&g_enc[b * NPTS + n], ~__float_as_uint(d2));
    }

    // ---- L1: last block of this (batch, src-chunk) 32-block group ----
    if (tid == 0) {
        __threadfence();                       // publish REDG results
        int prev = atomicAdd(&g_cnt1[b * SRC_CHUNKS + sc], 1);
        amLast1 = (prev == TSPLIT - 1);
        if (amLast1) g_cnt1[b * SRC_CHUNKS + sc] = 0;  // reset for replay
    }
    __syncthreads();
    if (amLast1) {
        __threadfence();                       // acquire peers' REDG writes
        // 512 points: exactly one uint4 per thread; read, reset, decode, sum.
        uint4* pe = (uint4*)(g_enc + (size_t)b * NPTS + src0);
        uint4 v = pe[tid];
        pe[tid] = make_uint4(0u, 0u, 0u, 0u);  // reset identity for next replay
        shred[tid] = __uint_as_float(~v.x) + __uint_as_float(~v.y) +
                     __uint_as_float(~v.z) + __uint_as_float(~v.w);
        __syncthreads();
        for (int o = THREADS / 2; o > 0; o >>= 1) {
            if (tid < o) shred[tid] += shred[tid + o];
            __syncthreads();
        }
        // ---- L2: last chunk-finisher of this batch sums 8 chunk sums ----
        if (tid == 0) {
            g_csum[b * SRC_CHUNKS + sc] = shred[0];
            __threadfence();
            int prev = atomicAdd(&g_cnt2[b], 1);
            amLast2 = (prev == SRC_CHUNKS - 1);
            if (amLast2) g_cnt2[b] = 0;        // reset for replay
        }
        __syncthreads();
        if (amLast2 && tid == 0) {
            __threadfence();
            float tot = 0.0f;
#pragma unroll
            for (int t = 0; t < SRC_CHUNKS; t++) tot += g_csum[b * SRC_CHUNKS + t];
            out[b] = tot * (1.0f / (3.0f * NPTS));
        }
    }
}

extern "C" void kernel_launch(void* const* d_in, const int* in_sizes, int n_in,
                              void* d_out, int out_size) {
    const float* src = (const float*)d_in[0];  // [B,3,N]
    const float* tgt = (const float*)d_in[1];  // [B,3,M]
    float* out = (float*)d_out;                // [B]

    dim3 grid(TSPLIT, SRC_CHUNKS, BATCH);      // 32 x 8 x 8 = 2048 blocks
    nn_kernel<<<grid, THREADS>>>(src, tgt, out);
}

// round 15
// speedup vs baseline: 8.0972x; 1.0707x over previous
#include <cuda_runtime.h>
#include <cstdint>

// KDPointToPointLoss: loss[b] = (1/(3N)) * sum_n min_m ||s[b,:,n] - t[b,:,m]||^2
// B=8, C=3, N=M=4096 (fixed by dataset).
//
// Dense exact fp32. score(n,m) = |t_m|^2 - 2 s_n.t_m (monotone in d2).
// Main loop sits at the fp32 FMA-pipe wall (402M FMAs ~ 22.4us; scalar rt2 and
// packed FFMA2 rt4 have identical pipe time — FFMA2 frees issue slots).
// Targets in smem as two interleaved 16B words per pair -> 2x LDS.128 per j2;
// fma.rn.f32x2 x3 + 2 scalar FMNMX per (pair, point). Inner loop FULLY
// UNROLLED (64 iters) to remove loop-overhead issue slots.
//
// Combine: enc(d2) = ~bits(d2); for d2 >= 0 min-d2 == max-enc, identity 0.
// No-return atomicMax (REDG); zero-init IS the identity; finishers reset to 0.
// Two-level fused reduction pipelined into the wave:
//  L1: last block of each (batch, src-chunk) 32-block group sums its 512 pts.
//  L2: last L1 finisher per batch sums 8 chunk sums in fixed order -> out[b].
// All counters self-reset -> graph-replay safe; orders fixed -> deterministic.

#define BATCH 8
#define NPTS  4096
#define MPTS  4096

#define THREADS   128
#define ILP       4                       // source points per thread
#define SRC_PER_BLOCK (THREADS * ILP)     // 512
#define SRC_CHUNKS (NPTS / SRC_PER_BLOCK) // 8
#define TSPLIT    32                      // target splits
#define TC        (MPTS / TSPLIT)         // 128 targets per block
#define TC2       (TC / 2)                // 64 packed pairs

__device__ unsigned int g_enc[BATCH * NPTS];          // ~bits(min d2); 0 = identity
__device__ float        g_csum[BATCH * SRC_CHUNKS];   // per-chunk sums
__device__ int          g_cnt1[BATCH * SRC_CHUNKS];   // L1 counters (to TSPLIT)
__device__ int          g_cnt2[BATCH];                // L2 counters (to SRC_CHUNKS)

__device__ __forceinline__ unsigned long long ffma2(
    unsigned long long a, unsigned long long b, unsigned long long c) {
    unsigned long long d;
    asm("fma.rn.f32x2 %0, %1, %2, %3;" : "=l"(d) : "l"(a), "l"(b), "l"(c));
    return d;
}
__device__ __forceinline__ unsigned long long pack2(float lo, float hi) {
    unsigned long long r;
    asm("mov.b64 %0, {%1, %2};" : "=l"(r) : "f"(lo), "f"(hi));
    return r;
}
__device__ __forceinline__ void unpack2(unsigned long long v, float& lo, float& hi) {
    asm("mov.b64 {%0, %1}, %2;" : "=f"(lo), "=f"(hi) : "l"(v));
}

__global__ __launch_bounds__(THREADS) void nn_kernel(
    const float* __restrict__ src, const float* __restrict__ tgt,
    float* __restrict__ out) {
    // Interleaved: sxy[j2] = {packed x pair, packed y pair},
    //              szw[j2] = {packed z pair, packed |t|^2 pair} -> LDS.128.
    __shared__ ulonglong2 sxy[TC2], szw[TC2];
    __shared__ float shred[THREADS];
    __shared__ int amLast1, amLast2;

    const int ts   = blockIdx.x;               // target split
    const int sc   = blockIdx.y;               // source chunk
    const int src0 = sc * SRC_PER_BLOCK;
    const int b    = blockIdx.z;
    const int tid  = threadIdx.x;
    const int tgt0 = ts * TC;

    // Cooperative packed load of this target chunk (TC2 = 64 < THREADS).
    const float2* tx = (const float2*)(tgt + (size_t)b * 3 * MPTS + 0 * MPTS + tgt0);
    const float2* ty = (const float2*)(tgt + (size_t)b * 3 * MPTS + 1 * MPTS + tgt0);
    const float2* tz = (const float2*)(tgt + (size_t)b * 3 * MPTS + 2 * MPTS + tgt0);
    if (tid < TC2) {
        int j2 = tid;
        float2 x = tx[j2];
        float2 y = ty[j2];
        float2 z = tz[j2];
        float w0 = fmaf(x.x, x.x, fmaf(y.x, y.x, z.x * z.x));
        float w1 = fmaf(x.y, x.y, fmaf(y.y, y.y, z.y * z.y));
        sxy[j2] = make_ulonglong2(pack2(x.x, x.y), pack2(y.x, y.y));
        szw[j2] = make_ulonglong2(pack2(z.x, z.y), pack2(w0, w1));
    }

    // Per-thread source points: packed duplicated coefficients (-2s, -2s).
    const float* sb = src + (size_t)b * 3 * NPTS;
    unsigned long long cx2[ILP], cy2[ILP], cz2[ILP];
    float s2[ILP], mnLo[ILP], mnHi[ILP];
#pragma unroll
    for (int p = 0; p < ILP; p++) {
        int n = src0 + p * THREADS + tid;
        float sx = sb[0 * NPTS + n];
        float sy = sb[1 * NPTS + n];
        float sz = sb[2 * NPTS + n];
        cx2[p] = pack2(-2.0f * sx, -2.0f * sx);
        cy2[p] = pack2(-2.0f * sy, -2.0f * sy);
        cz2[p] = pack2(-2.0f * sz, -2.0f * sz);
        s2[p]  = fmaf(sx, sx, fmaf(sy, sy, sz * sz));
        mnLo[p] = 1e30f;
        mnHi[p] = 1e30f;
    }
    __syncthreads();

    // Main loop, FULLY UNROLLED (TC2=64): per j2 (2 targets):
    // 2 LDS.128 + ILP*(3 FFMA2 + 2 FMNMX), no loop-overhead slots.
#pragma unroll
    for (int j2 = 0; j2 < TC2; j2++) {
        ulonglong2 vxy = sxy[j2];
        ulonglong2 vzw = szw[j2];
#pragma unroll
        for (int p = 0; p < ILP; p++) {
            unsigned long long acc = ffma2(cz2[p], vzw.x, vzw.y);
            acc = ffma2(cy2[p], vxy.y, acc);
            acc = ffma2(cx2[p], vxy.x, acc);
            float lo, hi;
            unpack2(acc, lo, hi);
            mnLo[p] = fminf(mnLo[p], lo);
            mnHi[p] = fminf(mnHi[p], hi);
        }
    }

    // Combine across target splits: min-d2 == max-enc, identity 0 (REDG).
#pragma unroll
    for (int p = 0; p < ILP; p++) {
        int n = src0 + p * THREADS + tid;
        float d2 = fmaxf(fminf(mnLo[p], mnHi[p]) + s2[p], 0.0f);
        atomicMax(&g_enc[b * NPTS + n], ~__float_as_uint(d2));
    }

    // ---- L1: last block of this (batch, src-chunk) 32-block group ----
    if (tid == 0) {
        __threadfence();                       // publish REDG results
        int prev = atomicAdd(&g_cnt1[b * SRC_CHUNKS + sc], 1);
        amLast1 = (prev == TSPLIT - 1);
        if (amLast1) g_cnt1[b * SRC_CHUNKS + sc] = 0;  // reset for replay
    }
    __syncthreads();
    if (amLast1) {
        __threadfence();                       // acquire peers' REDG writes
        // 512 points: exactly one uint4 per thread; read, reset, decode, sum.
        uint4* pe = (uint4*)(g_enc + (size_t)b * NPTS + src0);
        uint4 v = pe[tid];
        pe[tid] = make_uint4(0u, 0u, 0u, 0u);  // reset identity for next replay
        shred[tid] = __uint_as_float(~v.x) + __uint_as_float(~v.y) +
                     __uint_as_float(~v.z) + __uint_as_float(~v.w);
        __syncthreads();
        for (int o = THREADS / 2; o > 0; o >>= 1) {
            if (tid < o) shred[tid] += shred[tid + o];
            __syncthreads();
        }
        // ---- L2: last chunk-finisher of this batch sums 8 chunk sums ----
        if (tid == 0) {
            g_csum[b * SRC_CHUNKS + sc] = shred[0];
            __threadfence();
            int prev = atomicAdd(&g_cnt2[b], 1);
            amLast2 = (prev == SRC_CHUNKS - 1);
            if (amLast2) g_cnt2[b] = 0;        // reset for replay
        }
        __syncthreads();
        if (amLast2 && tid == 0) {
            __threadfence();
            float tot = 0.0f;
#pragma unroll
            for (int t = 0; t < SRC_CHUNKS; t++) tot += g_csum[b * SRC_CHUNKS + t];
            out[b] = tot * (1.0f / (3.0f * NPTS));
        }
    }
}

extern "C" void kernel_launch(void* const* d_in, const int* in_sizes, int n_in,
                              void* d_out, int out_size) {
    const float* src = (const float*)d_in[0];  // [B,3,N]
    const float* tgt = (const float*)d_in[1];  // [B,3,M]
    float* out = (float*)d_out;                // [B]

    dim3 grid(TSPLIT, SRC_CHUNKS, BATCH);      // 32 x 8 x 8 = 2048 blocks
    nn_kernel<<<grid, THREADS>>>(src, tgt, out);
}